// round 2
// baseline (speedup 1.0000x reference)
#include <cuda_runtime.h>
#include <cstdint>

// Problem constants (fixed by the dataset)
#define B_    4
#define N_    8192
#define M_    2048
#define K_    32
#define C_    64
#define NBINS 16

#define MPB     16    // m-rows per block
#define THREADS 256
// phase 2: 16 threads per m-row, 4 channels (float4) per thread

// Padded smem strides (avoid 2-way conflicts between the two m-groups in a warp)
#define SCO_STRIDE (K_ * 8 + 8)   // floats per m-row of coeffs (1056B: 16B aligned, bank-shifted)
#define SPK_STRIDE (K_ + 1)

__device__ int g_idx_is64;

// Detect whether nn_index buffer is int64 or int32.
// Reads only the first 4096 int32 words (16 KB) — safe under both layouts
// (int32 buffer is 1 MB). For int64 data with values in [0, 8192), every odd
// 32-bit word (the high half) is zero; for int32 data the odd words are random
// indices, essentially never all zero. Deterministic given the input.
__global__ void detect_idx_dtype_kernel(const int* __restrict__ words) {
    __shared__ int any_nonzero;
    if (threadIdx.x == 0) any_nonzero = 0;
    __syncthreads();
    int local = 0;
    for (int i = threadIdx.x; i < 2048; i += blockDim.x) {
        if (words[2 * i + 1] != 0) local = 1;
    }
    if (local) atomicOr(&any_nonzero, 1);
    __syncthreads();
    if (threadIdx.x == 0) g_idx_is64 = any_nonzero ? 0 : 1;
}

__global__ __launch_bounds__(THREADS) void fuzzy_sphere_kernel(
    const float* __restrict__ database,      // (B, N, 3)
    const float* __restrict__ query,         // (B, M, 3)
    const void*  __restrict__ nn_index_raw,  // (B, M, K) int64 or int32
    const float* __restrict__ nn_dist,       // (B, M, K)
    const float* __restrict__ feats,         // (B, N, C)
    const float* __restrict__ fw,            // (NBINS, C, 1)
    float* __restrict__ out)                 // (B, M, C)
{
    __shared__ float    sw[NBINS * C_];            // 4 KB weight table
    __shared__ float    scoef[MPB * SCO_STRIDE];   // coeffs, 8 per (m,k)
    __shared__ uint32_t spack[MPB * SPK_STRIDE];   // 8 packed 4-bit bins per (m,k)
    __shared__ int      soff [MPB * SPK_STRIDE];   // feature row offset (b*N+idx)*C

    const int tid = threadIdx.x;
    const int gm0 = blockIdx.x * MPB;

    // Load the 16x64 weight table into smem
    #pragma unroll
    for (int i = tid; i < NBINS * C_; i += THREADS) sw[i] = fw[i];

    const int is64 = g_idx_is64;

    // ---------------- Phase 1: bins + coeffs, one task per (m,k) --------------
    #pragma unroll
    for (int task = tid; task < MPB * K_; task += THREADS) {
        const int mi = task >> 5;           // task / K_
        const int k  = task & (K_ - 1);
        const int gm = gm0 + mi;            // flattened b*M + m
        const int b  = gm >> 11;            // gm / M_

        int nidx;
        if (is64) nidx = (int)((const long long*)nn_index_raw)[(size_t)gm * K_ + k];
        else      nidx = ((const int*)nn_index_raw)[(size_t)gm * K_ + k];

        const float d  = nn_dist[(size_t)gm * K_ + k];
        const float qx = query[gm * 3 + 0];
        const float qy = query[gm * 3 + 1];
        const float qz = query[gm * 3 + 2];
        const float* dbp = database + ((size_t)b * N_ + nidx) * 3;
        const float x = dbp[0] - qx;
        const float y = dbp[1] - qy;
        const float z = dbp[2] - qz;

        const float azimuth = atan2f(y, x) + 3.14159265358979323846f;
        float ct = z / (d + 1e-8f);
        ct = fminf(fmaxf(ct, -1.0f), 1.0f);
        const float elevation = acosf(ct);

        const float SC = 0.63661977236758134f;   // 4/(2pi) == 2/pi
        const float ab = azimuth   * SC;
        const float eb = elevation * SC;
        float rb = d / 0.05f;
        rb = fminf(fmaxf(rb, 0.0f), 2.0f - 1e-6f);

        const float afl = floorf(ab), efl = floorf(eb), rfl = floorf(rb);
        const float afr = ab - afl,   efr = eb - efl,   rfr = rb - rfl;
        const float ai = 1.0f - afr,  ei = 1.0f - efr,  ri = 1.0f - rfr;

        const int a0 = ((int)afl) & 3;
        const int a1 = (a0 + 1) & 3;
        const int e0 = min((int)efl, 1);         // efl >= 0 (acos >= 0)
        const int e1 = min((int)efl + 1, 1);
        const int r0 = min((int)rfl, 1);         // rfl in {0,1}
        const int r1 = min((int)rfl + 1, 1);

        // Corner order matches the reference stack order
        float c[8];
        c[0] = ai  * ei  * ri;  c[1] = afr * ei  * ri;
        c[2] = ai  * efr * ri;  c[3] = afr * efr * ri;
        c[4] = ai  * ei  * rfr; c[5] = afr * ei  * rfr;
        c[6] = ai  * efr * rfr; c[7] = afr * efr * rfr;

        uint32_t p = 0;
        p |= (uint32_t)(((a0 * 2 + e0) * 2) + r0) << 0;
        p |= (uint32_t)(((a1 * 2 + e0) * 2) + r0) << 4;
        p |= (uint32_t)(((a0 * 2 + e1) * 2) + r0) << 8;
        p |= (uint32_t)(((a1 * 2 + e1) * 2) + r0) << 12;
        p |= (uint32_t)(((a0 * 2 + e0) * 2) + r1) << 16;
        p |= (uint32_t)(((a1 * 2 + e0) * 2) + r1) << 20;
        p |= (uint32_t)(((a0 * 2 + e1) * 2) + r1) << 24;
        p |= (uint32_t)(((a1 * 2 + e1) * 2) + r1) << 28;

        spack[mi * SPK_STRIDE + k] = p;
        soff [mi * SPK_STRIDE + k] = (b * N_ + nidx) * C_;
        float* cdst = &scoef[mi * SCO_STRIDE + k * 8];
        #pragma unroll
        for (int e = 0; e < 8; e++) cdst[e] = c[e];
    }
    __syncthreads();

    // ---------------- Phase 2: accumulate channels ---------------------------
    const int sub = tid >> 4;            // which m-row (0..15)
    const int t4  = (tid & 15) * 4;      // channel base (float4)
    const int gm  = gm0 + sub;

    const float*    mycoef = &scoef[sub * SCO_STRIDE];
    const uint32_t* mypack = &spack[sub * SPK_STRIDE];
    const int*      myoff  = &soff [sub * SPK_STRIDE];

    float4 acc = make_float4(0.f, 0.f, 0.f, 0.f);

    #pragma unroll 4
    for (int k = 0; k < K_; k++) {
        const int off = myoff[k];
        const float4 nf = *(const float4*)(feats + off + t4);

        const uint32_t p  = mypack[k];
        const float4   cA = *(const float4*)(mycoef + k * 8 + 0);
        const float4   cB = *(const float4*)(mycoef + k * 8 + 4);
        const float cc[8] = {cA.x, cA.y, cA.z, cA.w, cB.x, cB.y, cB.z, cB.w};

        float4 ws = make_float4(0.f, 0.f, 0.f, 0.f);
        #pragma unroll
        for (int e = 0; e < 8; e++) {
            const int bin = (p >> (4 * e)) & 15;
            const float4 w = *(const float4*)(sw + bin * C_ + t4);
            ws.x += cc[e] * w.x;
            ws.y += cc[e] * w.y;
            ws.z += cc[e] * w.z;
            ws.w += cc[e] * w.w;
        }
        acc.x += nf.x * ws.x;
        acc.y += nf.y * ws.y;
        acc.z += nf.z * ws.z;
        acc.w += nf.w * ws.w;
    }

    *(float4*)(out + (size_t)gm * C_ + t4) = acc;
}

extern "C" void kernel_launch(void* const* d_in, const int* in_sizes, int n_in,
                              void* d_out, int out_size) {
    const float* database = (const float*)d_in[0];
    const float* query    = (const float*)d_in[1];
    const void*  nn_index = (const void*) d_in[2];
    // d_in[3] = nn_count (unused by the reference einsum)
    const float* nn_dist  = (const float*)d_in[4];
    const float* feats    = (const float*)d_in[5];
    const float* fw       = (const float*)d_in[6];
    float* out = (float*)d_out;

    detect_idx_dtype_kernel<<<1, 256>>>((const int*)nn_index);

    const int blocks = (B_ * M_) / MPB;   // 512
    fuzzy_sphere_kernel<<<blocks, THREADS>>>(
        database, query, nn_index, nn_dist, feats, fw, out);
}

// round 3
// speedup vs baseline: 1.0441x; 1.0441x over previous
#include <cuda_runtime.h>
#include <cstdint>

// Problem constants (fixed by the dataset)
#define B_    4
#define N_    8192
#define M_    2048
#define K_    32
#define C_    64
#define NBINS 16

#define MPB     8     // m-rows per block (one warp per row in phase 2)
#define THREADS 256

#define SCO_STRIDE (K_ * 8 + 8)   // floats per m-row of coeffs

__device__ int g_idx_is64;

// Detect whether nn_index buffer is int64 or int32 (values < 8192 => high
// words of int64 all zero; int32 data makes odd words random). Deterministic.
__global__ void detect_idx_dtype_kernel(const int* __restrict__ words) {
    __shared__ int any_nonzero;
    if (threadIdx.x == 0) any_nonzero = 0;
    __syncthreads();
    int local = 0;
    for (int i = threadIdx.x; i < 2048; i += blockDim.x) {
        if (words[2 * i + 1] != 0) local = 1;
    }
    if (local) atomicOr(&any_nonzero, 1);
    __syncthreads();
    if (threadIdx.x == 0) g_idx_is64 = any_nonzero ? 0 : 1;
}

__global__ __launch_bounds__(THREADS) void fuzzy_sphere_kernel(
    const float* __restrict__ database,      // (B, N, 3)
    const float* __restrict__ query,         // (B, M, 3)
    const void*  __restrict__ nn_index_raw,  // (B, M, K) int64 or int32
    const float* __restrict__ nn_dist,       // (B, M, K)
    const float* __restrict__ feats,         // (B, N, C)
    const float* __restrict__ fw,            // (NBINS, C, 1)
    float* __restrict__ out)                 // (B, M, C)
{
    __shared__ float sw[NBINS * C_];             // 4 KB weight table
    __shared__ float scoef[MPB * SCO_STRIDE];    // 8 coeffs per (m,k)
    __shared__ int2  spo[MPB * K_];              // {feature offset, packed bins}

    const int tid = threadIdx.x;
    const int gm0 = blockIdx.x * MPB;

    // Load the 16x64 weight table into smem
    #pragma unroll
    for (int i = tid; i < NBINS * C_; i += THREADS) sw[i] = fw[i];

    const int is64 = g_idx_is64;

    // ---------------- Phase 1: bins + coeffs, exactly one task per thread ----
    {
        const int mi = tid >> 5;            // m-row within block (0..7)
        const int k  = tid & 31;            // neighbor index
        const int gm = gm0 + mi;            // flattened b*M + m
        const int b  = gm >> 11;            // gm / M_

        int nidx;
        if (is64) nidx = (int)((const long long*)nn_index_raw)[(size_t)gm * K_ + k];
        else      nidx = ((const int*)nn_index_raw)[(size_t)gm * K_ + k];

        const float d  = nn_dist[(size_t)gm * K_ + k];
        const float qx = query[gm * 3 + 0];
        const float qy = query[gm * 3 + 1];
        const float qz = query[gm * 3 + 2];
        const float* dbp = database + ((size_t)b * N_ + nidx) * 3;
        const float x = dbp[0] - qx;
        const float y = dbp[1] - qy;
        const float z = dbp[2] - qz;

        const float azimuth = atan2f(y, x) + 3.14159265358979323846f;
        float ct = z / (d + 1e-8f);
        ct = fminf(fmaxf(ct, -1.0f), 1.0f);
        const float elevation = acosf(ct);

        const float SC = 0.63661977236758134f;   // 4/(2pi) == 2/pi
        const float ab = azimuth   * SC;
        const float eb = elevation * SC;
        float rb = d / 0.05f;
        rb = fminf(fmaxf(rb, 0.0f), 2.0f - 1e-6f);

        const float afl = floorf(ab), efl = floorf(eb), rfl = floorf(rb);
        const float afr = ab - afl,   efr = eb - efl,   rfr = rb - rfl;
        const float ai = 1.0f - afr,  ei = 1.0f - efr,  ri = 1.0f - rfr;

        const int a0 = ((int)afl) & 3;
        const int a1 = (a0 + 1) & 3;
        const int e0 = min((int)efl, 1);         // efl >= 0 (acos >= 0)
        const int e1 = min((int)efl + 1, 1);
        const int r0 = min((int)rfl, 1);         // rfl in {0,1}
        const int r1 = min((int)rfl + 1, 1);

        float c[8];
        c[0] = ai  * ei  * ri;  c[1] = afr * ei  * ri;
        c[2] = ai  * efr * ri;  c[3] = afr * efr * ri;
        c[4] = ai  * ei  * rfr; c[5] = afr * ei  * rfr;
        c[6] = ai  * efr * rfr; c[7] = afr * efr * rfr;

        uint32_t p = 0;
        p |= (uint32_t)(((a0 * 2 + e0) * 2) + r0) << 0;
        p |= (uint32_t)(((a1 * 2 + e0) * 2) + r0) << 4;
        p |= (uint32_t)(((a0 * 2 + e1) * 2) + r0) << 8;
        p |= (uint32_t)(((a1 * 2 + e1) * 2) + r0) << 12;
        p |= (uint32_t)(((a0 * 2 + e0) * 2) + r1) << 16;
        p |= (uint32_t)(((a1 * 2 + e0) * 2) + r1) << 20;
        p |= (uint32_t)(((a0 * 2 + e1) * 2) + r1) << 24;
        p |= (uint32_t)(((a1 * 2 + e1) * 2) + r1) << 28;

        spo[mi * K_ + k] = make_int2((b * N_ + nidx) * C_, (int)p);
        float* cdst = &scoef[mi * SCO_STRIDE + k * 8];
        #pragma unroll
        for (int e = 0; e < 8; e++) cdst[e] = c[e];
    }
    __syncthreads();

    // ---------------- Phase 2: one warp per m-row, float2 per lane -----------
    const int sub  = tid >> 5;           // m-row (0..7) == warp id
    const int lane = tid & 31;
    const int t2   = lane * 2;           // channel base (float2)
    const int gm   = gm0 + sub;

    const float* mycoef = &scoef[sub * SCO_STRIDE];
    const int2*  mypo   = &spo[sub * K_];

    float2 acc = make_float2(0.f, 0.f);

    // Software pipeline: prefetch next iteration's gathered feature load.
    int2   po_n = mypo[0];
    float2 nf_n = *(const float2*)(feats + po_n.x + t2);

    #pragma unroll 8
    for (int k = 0; k < K_; k++) {
        const float2   nf = nf_n;
        const uint32_t p  = (uint32_t)po_n.y;
        if (k + 1 < K_) {
            po_n = mypo[k + 1];
            nf_n = *(const float2*)(feats + po_n.x + t2);
        }

        const float4 cA = *(const float4*)(mycoef + k * 8 + 0);
        const float4 cB = *(const float4*)(mycoef + k * 8 + 4);
        const float cc[8] = {cA.x, cA.y, cA.z, cA.w, cB.x, cB.y, cB.z, cB.w};

        float2 ws = make_float2(0.f, 0.f);
        #pragma unroll
        for (int e = 0; e < 8; e++) {
            const int bin = (p >> (4 * e)) & 15;
            const float2 w = *(const float2*)(sw + bin * C_ + t2);
            ws.x += cc[e] * w.x;
            ws.y += cc[e] * w.y;
        }
        acc.x += nf.x * ws.x;
        acc.y += nf.y * ws.y;
    }

    *(float2*)(out + (size_t)gm * C_ + t2) = acc;
}

extern "C" void kernel_launch(void* const* d_in, const int* in_sizes, int n_in,
                              void* d_out, int out_size) {
    const float* database = (const float*)d_in[0];
    const float* query    = (const float*)d_in[1];
    const void*  nn_index = (const void*) d_in[2];
    // d_in[3] = nn_count (unused by the reference einsum)
    const float* nn_dist  = (const float*)d_in[4];
    const float* feats    = (const float*)d_in[5];
    const float* fw       = (const float*)d_in[6];
    float* out = (float*)d_out;

    detect_idx_dtype_kernel<<<1, 256>>>((const int*)nn_index);

    const int blocks = (B_ * M_) / MPB;   // 1024
    fuzzy_sphere_kernel<<<blocks, THREADS>>>(
        database, query, nn_index, nn_dist, feats, fw, out);
}

// round 8
// speedup vs baseline: 1.0922x; 1.0461x over previous
#include <cuda_runtime.h>
#include <cstdint>

// Problem constants (fixed by the dataset)
#define B_    4
#define N_    8192
#define M_    2048
#define K_    32
#define C_    64
#define NBINS 16

#define MPB     8     // m-rows per block (one warp per row in phase 2)
#define THREADS 256

#define G_STRIDE 36   // floats per (m,k) g-record: 32 data + 4 pad (kills STS conflicts)

typedef unsigned long long ull;

__device__ int g_idx_is64;

// Detect whether nn_index buffer is int64 or int32 (values < 8192 => high
// words of int64 all zero; int32 data makes odd words random). Deterministic.
__global__ void detect_idx_dtype_kernel(const int* __restrict__ words) {
    __shared__ int any_nonzero;
    if (threadIdx.x == 0) any_nonzero = 0;
    __syncthreads();
    int local = 0;
    for (int i = threadIdx.x; i < 2048; i += blockDim.x) {
        if (words[2 * i + 1] != 0) local = 1;
    }
    if (local) atomicOr(&any_nonzero, 1);
    __syncthreads();
    if (threadIdx.x == 0) g_idx_is64 = any_nonzero ? 0 : 1;
}

// Packed fp32x2 ops (Blackwell): one instruction, two fp32 lanes.
#define FMA2(d, a, b, c) \
    asm("fma.rn.f32x2 %0, %1, %2, %3;" : "=l"(d) : "l"(a), "l"(b), "l"(c))
#define ADD2(d, a, b) \
    asm("add.rn.f32x2 %0, %1, %2;" : "=l"(d) : "l"(a), "l"(b))

__global__ __launch_bounds__(THREADS) void fuzzy_sphere_kernel(
    const float* __restrict__ database,      // (B, N, 3)
    const float* __restrict__ query,         // (B, M, 3)
    const void*  __restrict__ nn_index_raw,  // (B, M, K) int64 or int32
    const float* __restrict__ nn_dist,       // (B, M, K)
    const float* __restrict__ feats,         // (B, N, C)
    const float* __restrict__ fw,            // (NBINS, C, 1)
    float* __restrict__ out)                 // (B, M, C)
{
    __shared__ float sg[MPB * K_ * G_STRIDE];  // duplicated g-pairs, 36.9 KB
    __shared__ int   soff[MPB * K_];           // feature row offsets

    const int tid = threadIdx.x;
    const int gm0 = blockIdx.x * MPB;

    // -------- Load this lane's weight columns into registers (16 bins x f32x2)
    const int lane = tid & 31;
    const int t2   = lane * 2;                 // channel pair base
    ull wreg[NBINS];
    #pragma unroll
    for (int i = 0; i < NBINS; i++)
        wreg[i] = *(const ull*)(fw + i * C_ + t2);

    const int is64 = g_idx_is64;

    // ---------------- Phase 1: factorized bin coefficients, one task/thread --
    {
        const int mi = tid >> 5;            // m-row within block (0..7)
        const int k  = lane;                // neighbor index
        const int gm = gm0 + mi;            // flattened b*M + m
        const int b  = gm >> 11;            // gm / M_

        int nidx;
        if (is64) nidx = (int)((const long long*)nn_index_raw)[(size_t)gm * K_ + k];
        else      nidx = ((const int*)nn_index_raw)[(size_t)gm * K_ + k];

        const float d  = nn_dist[(size_t)gm * K_ + k];
        const float qx = query[gm * 3 + 0];
        const float qy = query[gm * 3 + 1];
        const float qz = query[gm * 3 + 2];
        const float* dbp = database + ((size_t)b * N_ + nidx) * 3;
        const float x = dbp[0] - qx;
        const float y = dbp[1] - qy;
        const float z = dbp[2] - qz;

        const float azimuth = atan2f(y, x) + 3.14159265358979323846f;
        float ct = z / (d + 1e-8f);
        ct = fminf(fmaxf(ct, -1.0f), 1.0f);
        const float elevation = acosf(ct);

        const float SC = 0.63661977236758134f;   // 4/(2pi) == 2/pi
        const float ab = azimuth   * SC;
        const float eb = elevation * SC;
        float rb = d / 0.05f;
        rb = fminf(fmaxf(rb, 0.0f), 2.0f - 1e-6f);

        const float afl = floorf(ab), efl = floorf(eb), rfl = floorf(rb);
        const float afr = ab - afl,   efr = eb - efl,   rfr = rb - rfl;
        const float ai = 1.0f - afr,  ei = 1.0f - efr,  ri = 1.0f - rfr;

        const int a0 = ((int)afl) & 3;
        const int ef = (int)efl;             // 0,1,(2 at poles)
        const int rf = (int)rfl;             // 0 or 1

        // Factorized axis coefficient vectors (exact: ei+efr == 1, ri+rfr == 1)
        const float FE0 = (ef == 0) ? ei  : 0.0f;
        const float FE1 = (ef == 0) ? efr : 1.0f;
        const float FR0 = (rf == 0) ? ri  : 0.0f;
        const float FR1 = (rf == 0) ? rfr : 1.0f;

        const float t00 = FE0 * FR0, t01 = FE0 * FR1;
        const float t10 = FE1 * FR0, t11 = FE1 * FR1;

        // FA[A]: ai at a0, afr at a1=(a0+1)&3, else 0 — no dynamic indexing
        const float fa0 = (a0 == 0) ? ai : ((a0 == 3) ? afr : 0.0f);
        const float fa1 = (a0 == 1) ? ai : ((a0 == 0) ? afr : 0.0f);
        const float fa2 = (a0 == 2) ? ai : ((a0 == 1) ? afr : 0.0f);
        const float fa3 = (a0 == 3) ? ai : ((a0 == 2) ? afr : 0.0f);

        float* dst = sg + (mi * K_ + k) * G_STRIDE;
        const float fa[4] = {fa0, fa1, fa2, fa3};
        #pragma unroll
        for (int A = 0; A < 4; A++) {
            const float g00 = fa[A] * t00, g01 = fa[A] * t01;
            const float g10 = fa[A] * t10, g11 = fa[A] * t11;
            ((float4*)dst)[2 * A + 0] = make_float4(g00, g00, g01, g01);
            ((float4*)dst)[2 * A + 1] = make_float4(g10, g10, g11, g11);
        }

        soff[mi * K_ + k] = (b * N_ + nidx) * C_;
    }
    __syncthreads();

    // ---------------- Phase 2: one warp per m-row, f32x2 per lane ------------
    const int sub = tid >> 5;            // m-row (0..7) == warp id
    const int gm  = gm0 + sub;

    const float* mygd  = sg + sub * K_ * G_STRIDE;
    const int*   myoff = soff + sub * K_;

    ull acc = 0;                          // f32x2 (0,0)

    // Software pipeline the gathered feature load one iteration ahead.
    int off_n = myoff[0];
    ull nf_n  = *(const ull*)(feats + off_n + t2);

    #pragma unroll 4
    for (int k = 0; k < K_; k++) {
        const ull nf = nf_n;
        if (k + 1 < K_) {
            off_n = myoff[k + 1];
            nf_n  = *(const ull*)(feats + off_n + t2);
        }

        // 16 duplicated g-pairs for this k (broadcast LDS.128 x 8)
        const ulonglong2* gp = (const ulonglong2*)(mygd + k * G_STRIDE);

        ull ws0 = 0, ws1 = 0, ws2 = 0, ws3 = 0;
        #pragma unroll
        for (int j = 0; j < 8; j += 2) {
            const ulonglong2 ua = gp[j];
            const ulonglong2 ub = gp[j + 1];
            FMA2(ws0, ua.x, wreg[2 * j + 0], ws0);
            FMA2(ws1, ua.y, wreg[2 * j + 1], ws1);
            FMA2(ws2, ub.x, wreg[2 * j + 2], ws2);
            FMA2(ws3, ub.y, wreg[2 * j + 3], ws3);
        }
        ull wsA, wsB, ws;
        ADD2(wsA, ws0, ws1);
        ADD2(wsB, ws2, ws3);
        ADD2(ws, wsA, wsB);
        FMA2(acc, nf, ws, acc);
    }

    *(ull*)(out + (size_t)gm * C_ + t2) = acc;
}

extern "C" void kernel_launch(void* const* d_in, const int* in_sizes, int n_in,
                              void* d_out, int out_size) {
    const float* database = (const float*)d_in[0];
    const float* query    = (const float*)d_in[1];
    const void*  nn_index = (const void*) d_in[2];
    // d_in[3] = nn_count (unused by the reference einsum)
    const float* nn_dist  = (const float*)d_in[4];
    const float* feats    = (const float*)d_in[5];
    const float* fw       = (const float*)d_in[6];
    float* out = (float*)d_out;

    detect_idx_dtype_kernel<<<1, 256>>>((const int*)nn_index);

    const int blocks = (B_ * M_) / MPB;   // 1024
    fuzzy_sphere_kernel<<<blocks, THREADS>>>(
        database, query, nn_index, nn_dist, feats, fw, out);
}